// round 9
// baseline (speedup 1.0000x reference)
#include <cuda_runtime.h>
#include <cuda_fp16.h>
#include <cstdint>

#define D_    512
#define NQ_   16384
#define NL_   1024

// ============================ scratch ============================
__device__ __half g_gA[NQ_ * D_];      // guide token-major fp16
__device__ __half g_lA[NL_ * D_];      // low token-major fp16
__device__ __half g_W[4][D_ * D_];     // q,k,v,m weights fp16 (k,v contiguous)
__device__ __half g_q[NQ_ * D_];       // q fp16
__device__ float  g_KV[NL_ * 1024];    // fused K|V per token
__device__ __half g_msg[NQ_ * D_];
__device__ float  g_mT[NQ_ * D_];

// ============================ helpers ============================
__device__ __forceinline__ uint32_t smem_u32(const void* p) {
    uint32_t a;
    asm("{ .reg .u64 t; cvta.to.shared.u64 t, %1; cvt.u32.u64 %0, t; }" : "=r"(a) : "l"(p));
    return a;
}
__device__ __forceinline__ void cp16(uint32_t s, const void* g) {
    asm volatile("cp.async.cg.shared.global [%0], [%1], 16;" :: "r"(s), "l"(g));
}
#define CP_COMMIT() asm volatile("cp.async.commit_group;" ::: "memory")
#define CP_WAIT(n)  asm volatile("cp.async.wait_group %0;" :: "n"(n) : "memory")

__device__ __forceinline__ void ldsm_x4(uint32_t* r, uint32_t addr) {
    asm volatile("ldmatrix.sync.aligned.m8n8.x4.shared.b16 {%0,%1,%2,%3}, [%4];"
                 : "=r"(r[0]), "=r"(r[1]), "=r"(r[2]), "=r"(r[3]) : "r"(addr));
}
// NON-volatile: pure register op; lets the compiler interleave MMAs with LDSMs.
__device__ __forceinline__ void mma_f16(float* d, const uint32_t* a, uint32_t b0, uint32_t b1) {
    asm("mma.sync.aligned.m16n8k16.row.col.f32.f16.f16.f32 "
        "{%0,%1,%2,%3}, {%4,%5,%6,%7}, {%8,%9}, {%0,%1,%2,%3};"
        : "+f"(d[0]), "+f"(d[1]), "+f"(d[2]), "+f"(d[3])
        : "r"(a[0]), "r"(a[1]), "r"(a[2]), "r"(a[3]), "r"(b0), "r"(b1));
}
__device__ __forceinline__ uint32_t swz(int row, int seg) {
    return (uint32_t)(row * 64 + ((seg ^ ((row >> 1) & 3)) * 16));
}

// ============================ converts ============================
__global__ __launch_bounds__(256)
void wconv(const float* __restrict__ W0, const float* __restrict__ W1,
           const float* __restrict__ W2, const float* __restrict__ W3,
           __half* __restrict__ W) {
    const float* src = (blockIdx.y == 0) ? W0 : (blockIdx.y == 1) ? W1
                     : (blockIdx.y == 2) ? W2 : W3;
    const int i = blockIdx.x * 256 + threadIdx.x;
    W[(size_t)blockIdx.y * (D_ * D_) + i] = __float2half(src[i]);
}

__global__ __launch_bounds__(256)
void transpose_half(const float* __restrict__ x, __half* __restrict__ y, int N) {
    __shared__ float t[32][33];
    const int n0 = blockIdx.x * 32, c0 = blockIdx.y * 32;
    const int tx = threadIdx.x, ty = threadIdx.y;
#pragma unroll
    for (int j = 0; j < 32; j += 8)
        t[ty + j][tx] = x[(size_t)(c0 + ty + j) * N + n0 + tx];
    __syncthreads();
#pragma unroll
    for (int j = 0; j < 32; j += 8)
        y[(size_t)(n0 + ty + j) * D_ + c0 + tx] = __float2half(t[tx][ty + j]);
}

// ============================ GEMM body ============================
// C[m0+m, n0+n] = sum_k A[m,k]*B[n,k]. 5-stage cp.async, k-chunk 32.
// All chunk fragments LDSM'd up front; 32 MMAs follow (compiler-interleaved).
template<int OUT_HALF>
__device__ __forceinline__
void gemm_body(const __half* __restrict__ A, const __half* __restrict__ B,
               void* __restrict__ C, int ldc, int m0, int n0) {
    extern __shared__ char sm[];
    const int tid = threadIdx.x, lane = tid & 31, warp = tid >> 5;
    const int wm = (warp & 1) * 64, wn = (warp >> 1) * 32;
    const uint32_t s0 = smem_u32(sm);

    const int l_row = tid >> 1;
    const int l_s0  = (tid & 1) * 2;

#define LOAD_STAGE(BUF, K0) do {                                                \
    const uint32_t sb = s0 + (uint32_t)(BUF) * 16384u;                          \
    _Pragma("unroll")                                                           \
    for (int j = 0; j < 2; j++) {                                               \
        const int seg = l_s0 + j;                                               \
        const uint32_t so = swz(l_row, seg);                                    \
        cp16(sb + so,          A + (size_t)(m0 + l_row) * 512 + (K0) + seg * 8);\
        cp16(sb + 8192u + so,  B + (size_t)(n0 + l_row) * 512 + (K0) + seg * 8);\
    }                                                                           \
} while (0)

    int a_rb[4], a_rx[4];
#pragma unroll
    for (int mi = 0; mi < 4; mi++) {
        const int r = wm + mi * 16 + (lane & 15);
        a_rb[mi] = r * 64;
        a_rx[mi] = (r >> 1) & 3;
    }
    int b_rb[2], b_rx[2];
#pragma unroll
    for (int nt = 0; nt < 2; nt++) {
        const int r = wn + nt * 16 + (lane & 7) + ((lane >> 4) & 1) * 8;
        b_rb[nt] = r * 64;
        b_rx[nt] = (r >> 1) & 3;
    }
    const int a_sl = (lane >> 4) & 1;
    const int b_sl = (lane >> 3) & 1;

    float acc[4][4][4];
#pragma unroll
    for (int i = 0; i < 4; i++)
#pragma unroll
        for (int j = 0; j < 4; j++)
#pragma unroll
            for (int r = 0; r < 4; r++) acc[i][j][r] = 0.f;

    LOAD_STAGE(0, 0);  CP_COMMIT();
    LOAD_STAGE(1, 32); CP_COMMIT();
    LOAD_STAGE(2, 64); CP_COMMIT();
    LOAD_STAGE(3, 96); CP_COMMIT();

    int buf = 0, pbuf = 4;
    for (int ch = 0; ch < 16; ch++) {
        CP_WAIT(3);
        __syncthreads();
        if (ch < 12) LOAD_STAGE(pbuf, (ch + 4) * 32);
        CP_COMMIT();

        const uint32_t base = s0 + (uint32_t)buf * 16384u;

        // ---- LDSM everything for this k32 chunk up front ----
        uint32_t a[2][4][4], b[2][2][4];
#pragma unroll
        for (int ks = 0; ks < 2; ks++) {
            const int sa = ks * 2 + a_sl;
#pragma unroll
            for (int mi = 0; mi < 4; mi++)
                ldsm_x4(a[ks][mi], base + a_rb[mi] + ((sa ^ a_rx[mi]) * 16));
        }
#pragma unroll
        for (int ks = 0; ks < 2; ks++) {
            const int sb = ks * 2 + b_sl;
#pragma unroll
            for (int nt = 0; nt < 2; nt++)
                ldsm_x4(b[ks][nt], base + 8192u + b_rb[nt] + ((sb ^ b_rx[nt]) * 16));
        }
        // ---- 32 MMAs (non-volatile; compiler/ptxas interleaves with LDSM) ----
#pragma unroll
        for (int ks = 0; ks < 2; ks++)
#pragma unroll
            for (int mi = 0; mi < 4; mi++)
#pragma unroll
                for (int j = 0; j < 4; j++)
                    mma_f16(acc[mi][j], a[ks][mi],
                            b[ks][j >> 1][(j & 1) * 2], b[ks][j >> 1][(j & 1) * 2 + 1]);

        buf  = (buf == 4)  ? 0 : buf + 1;
        pbuf = (pbuf == 4) ? 0 : pbuf + 1;
    }

    const int g = lane >> 2, t4 = lane & 3;
#pragma unroll
    for (int mi = 0; mi < 4; mi++) {
#pragma unroll
        for (int j = 0; j < 4; j++) {
            const int row = m0 + wm + mi * 16 + g;
            const int col = n0 + wn + j * 8 + 2 * t4;
            if (OUT_HALF) {
                __half* Ch = (__half*)C;
                *(__half2*)(Ch + (size_t)row * ldc + col) =
                    __floats2half2_rn(acc[mi][j][0], acc[mi][j][1]);
                *(__half2*)(Ch + (size_t)(row + 8) * ldc + col) =
                    __floats2half2_rn(acc[mi][j][2], acc[mi][j][3]);
            } else {
                float* Cf = (float*)C;
                *(float2*)(Cf + (size_t)row * ldc + col)       = make_float2(acc[mi][j][0], acc[mi][j][1]);
                *(float2*)(Cf + (size_t)(row + 8) * ldc + col) = make_float2(acc[mi][j][2], acc[mi][j][3]);
            }
        }
    }
#undef LOAD_STAGE
}

__global__ __launch_bounds__(256, 2)
void gemm_qkv(const __half* __restrict__ gA, const __half* __restrict__ lA,
              const __half* __restrict__ W,
              __half* __restrict__ qb, float* __restrict__ KV) {
    const int bid = blockIdx.x;
    if (bid < 64) {
        const int m0 = (bid >> 3) * 128;
        const int n0 = (bid & 7) * 128;
        gemm_body<0>(lA, W + (size_t)(D_ * D_), KV, 1024, m0, n0);
    } else {
        const int b = bid - 64;
        const int m0 = (b >> 2) * 128;
        const int n0 = (b & 3) * 128;
        gemm_body<1>(gA, W, qb, 512, m0, n0);
    }
}

__global__ __launch_bounds__(256, 2)
void gemm_one(const __half* __restrict__ A, const __half* __restrict__ B,
              float* __restrict__ C) {
    gemm_body<0>(A, B, C, 512, blockIdx.x * 128, blockIdx.y * 128);
}

// ============================ attention ============================
// q fp16; KV fp32 [NL][1024]; msg fp16. 2 adjacent 4x4 tiles per block.
// smem layout per row: float4 index = d4*8 + h  -> compute reads are one
// 128B phase (8 consecutive float4 across heads), zero bank conflicts.
__global__ __launch_bounds__(256)
void attn(const __half* __restrict__ q, const float* __restrict__ KV,
          __half* __restrict__ msg) {
    extern __shared__ float4 s4[];
    float4* ks = s4;                  // 12 x 129
    float4* vs = ks + 12 * 129;       // 12 x 129

    const int by = blockIdx.y;
    const int xb = blockIdx.x * 2;
    const int tid = threadIdx.x;

    for (int t = tid; t < 3072; t += 256) {
        const int r = t >> 7, j = t & 127;            // j = d4*8 + h
        const int k = (r < 12) ? r : r - 12;
        const int ky = k >> 2, kx = k & 3;
        const int yy = min(max(by + ky - 1, 0), 31);
        const int xx = min(max(xb + kx - 1, 0), 31);
        const float4* row = (const float4*)(KV + (size_t)(yy * 32 + xx) * 1024);
        const int gi = (j & 7) * 16 + (j >> 3);       // gmem float4 idx = h*16 + d4
        if (r < 12) ks[k * 129 + j] = row[gi];
        else        vs[k * 129 + j] = row[128 + gi];
    }

    const int qi = tid & 15;
    const int h  = (tid >> 4) & 7;
    const int ti = tid >> 7;
    const int n = (4 * by + (qi >> 2)) * 128 + 4 * (xb + ti) + (qi & 3);

    float4 qr[16];
    {
        const __half2* qg = (const __half2*)(q + (size_t)n * D_ + h * 64);
#pragma unroll
        for (int i = 0; i < 16; i++) {
            const float2 a = __half22float2(qg[2 * i]);
            const float2 b = __half22float2(qg[2 * i + 1]);
            qr[i] = make_float4(a.x, a.y, b.x, b.y);
        }
    }
    __syncthreads();

    float sc[9];
#pragma unroll
    for (int ky = 0; ky < 3; ky++)
#pragma unroll
    for (int kx = 0; kx < 3; kx++) {
        const float4* kp = ks + (ky * 4 + kx + ti) * 129 + h;
        float s = 0.f;
#pragma unroll
        for (int d4 = 0; d4 < 16; d4++) {
            const float4 a = qr[d4], b = kp[d4 * 8];
            s = fmaf(a.x, b.x, s); s = fmaf(a.y, b.y, s);
            s = fmaf(a.z, b.z, s); s = fmaf(a.w, b.w, s);
        }
        sc[ky * 3 + kx] = s * 0.125f;
    }
    float mx = sc[0];
#pragma unroll
    for (int k = 1; k < 9; k++) mx = fmaxf(mx, sc[k]);
    float sum = 0.f;
#pragma unroll
    for (int k = 0; k < 9; k++) { sc[k] = __expf(sc[k] - mx); sum += sc[k]; }
    const float inv = 1.f / sum;
#pragma unroll
    for (int k = 0; k < 9; k++) sc[k] *= inv;

    __half2* om = (__half2*)(msg + (size_t)n * D_ + h * 64);
#pragma unroll 4
    for (int d4 = 0; d4 < 16; d4++) {
        float ax = 0.f, ay = 0.f, az = 0.f, aw = 0.f;
#pragma unroll
        for (int ky = 0; ky < 3; ky++)
#pragma unroll
        for (int kx = 0; kx < 3; kx++) {
            const float4 v = vs[(ky * 4 + kx + ti) * 129 + d4 * 8 + h];
            const float w = sc[ky * 3 + kx];
            ax = fmaf(w, v.x, ax); ay = fmaf(w, v.y, ay);
            az = fmaf(w, v.z, az); aw = fmaf(w, v.w, aw);
        }
        om[d4 * 2 + 0] = __floats2half2_rn(ax, ay);
        om[d4 * 2 + 1] = __floats2half2_rn(az, aw);
    }
}

// ============================ fused LayerNorm + transpose ============================
__global__ __launch_bounds__(256)
void ln_fused(const float* __restrict__ m, const float* __restrict__ gamma,
              const float* __restrict__ beta, float* __restrict__ out) {
    extern __shared__ float smf[];            // [32][513]
    __shared__ float smu[32], srs[32];
    const int n0 = blockIdx.x * 32;
    const int tid = threadIdx.x, lane = tid & 31, warp = tid >> 5;

    for (int idx = tid; idx < 32 * 128; idx += 256) {
        const int row = idx >> 7, c4 = idx & 127;
        const float4 v = *(const float4*)(m + (size_t)(n0 + row) * 512 + c4 * 4);
        float* d = smf + row * 513 + c4 * 4;
        d[0] = v.x; d[1] = v.y; d[2] = v.z; d[3] = v.w;
    }
    __syncthreads();

#pragma unroll
    for (int t = warp * 4; t < warp * 4 + 4; t++) {
        float s = 0.f, s2 = 0.f;
#pragma unroll
        for (int i = 0; i < 16; i++) {
            const float v = smf[t * 513 + lane + i * 32];
            s += v; s2 += v * v;
        }
#pragma unroll
        for (int o = 16; o; o >>= 1) {
            s  += __shfl_xor_sync(0xFFFFFFFFu, s, o);
            s2 += __shfl_xor_sync(0xFFFFFFFFu, s2, o);
        }
        if (lane == 0) {
            const float mu = s * (1.f / 512.f);
            smu[t] = mu;
            srs[t] = rsqrtf(s2 * (1.f / 512.f) - mu * mu + 1e-5f);
        }
    }
    __syncthreads();

    for (int idx = tid; idx < 32 * 512; idx += 256) {
        const int c = idx >> 5, nl = idx & 31;
        out[(size_t)c * NQ_ + n0 + nl] =
            (smf[nl * 513 + c] - smu[nl]) * srs[nl] * gamma[c] + beta[c];
    }
}

// ============================ launch ============================
extern "C" void kernel_launch(void* const* d_in, const int* in_sizes, int n_in,
                              void* d_out, int out_size) {
    const float* low   = (const float*)d_in[0];
    const float* guide = (const float*)d_in[1];
    const float* Wq    = (const float*)d_in[2];
    const float* Wk    = (const float*)d_in[3];
    const float* Wv    = (const float*)d_in[4];
    const float* Wm    = (const float*)d_in[5];
    const float* gamma = (const float*)d_in[6];
    const float* beta  = (const float*)d_in[7];
    float* out = (float*)d_out;

    __half *gA, *lA, *W, *qb, *msg;
    float *KV, *mT;
    cudaGetSymbolAddress((void**)&gA,  g_gA);
    cudaGetSymbolAddress((void**)&lA,  g_lA);
    cudaGetSymbolAddress((void**)&W,   g_W);
    cudaGetSymbolAddress((void**)&qb,  g_q);
    cudaGetSymbolAddress((void**)&KV,  g_KV);
    cudaGetSymbolAddress((void**)&msg, g_msg);
    cudaGetSymbolAddress((void**)&mT,  g_mT);

    const int SM_GEMM = 5 * 16384;       // 81920
    const int SM_ATTN = 24 * 129 * 16;   // 49536
    const int SM_LN   = 32 * 513 * 4;    // 65664
    cudaFuncSetAttribute(gemm_qkv, cudaFuncAttributeMaxDynamicSharedMemorySize, SM_GEMM);
    cudaFuncSetAttribute(gemm_one, cudaFuncAttributeMaxDynamicSharedMemorySize, SM_GEMM);
    cudaFuncSetAttribute(attn, cudaFuncAttributeMaxDynamicSharedMemorySize, SM_ATTN);
    cudaFuncSetAttribute(ln_fused, cudaFuncAttributeMaxDynamicSharedMemorySize, SM_LN);

    // One-time conversions
    wconv<<<dim3(D_ * D_ / 256, 4), 256>>>(Wq, Wk, Wv, Wm, W);
    transpose_half<<<dim3(NQ_ / 32, D_ / 32), dim3(32, 8)>>>(guide, gA, NQ_);
    transpose_half<<<dim3(NL_ / 32, D_ / 32), dim3(32, 8)>>>(low, lA, NL_);

    // Fused Q + KV projections
    gemm_qkv<<<576, 256, SM_GEMM>>>(gA, lA, W, qb, KV);

    // Windowed attention
    attn<<<dim3(16, 32), 256, SM_ATTN>>>(qb, KV, msg);

    // Output projection + fused LayerNorm/transpose
    gemm_one<<<dim3(NQ_ / 128, 4), 256, SM_GEMM>>>(msg, W + 3 * (size_t)(D_ * D_), mT);
    ln_fused<<<NQ_ / 32, 256, SM_LN>>>(mT, gamma, beta, out);
}